// round 16
// baseline (speedup 1.0000x reference)
#include <cuda_runtime.h>
#include <cstdint>

// Problem constants (fixed by the reference setup_inputs)
#define BATCH 2
#define SEQ   2048
#define DMODEL 1024
#define NHEAD 16
#define DK    64
#define MROWS (BATCH * SEQ)   // 4096

// Q is pre-scaled by 1/sqrt(dk) * log2(e) at the projection epilogue, so the
// attention softmax runs natively in base-2 (single MUFU per score).
#define QSCALE 0.18033688011112042f   // 0.125 * log2(e)

// Scratch
__device__ float g_Q[BATCH * NHEAD * SEQ * DK];   // tf32-valued
__device__ float g_K[BATCH * NHEAD * SEQ * DK];   // tf32-valued
__device__ float g_V[BATCH * NHEAD * SEQ * DK];   // tf32-valued
__device__ float g_O[BATCH * SEQ * DMODEL];       // tf32-valued (attn epilogue rounds)
__device__ float g_Ain[3][MROWS * DMODEL];        // tf32-rounded query/key/value
__device__ float g_Wt[4][DMODEL * DMODEL];        // tf32-rounded Wq/Wk/Wv/Wout

// ---------------------------------------------------------------------------
// helpers
// ---------------------------------------------------------------------------
__device__ __forceinline__ unsigned f2tf32(float f) {
    unsigned u;
    asm("cvt.rna.tf32.f32 %0, %1;" : "=r"(u) : "f"(f));
    return u;
}

__device__ __forceinline__ float ex2f(float x) {
    float r;
    asm("ex2.approx.f32 %0, %1;" : "=f"(r) : "f"(x));
    return r;
}

__device__ __forceinline__ void mma_tf32(float c[4], const unsigned a[4], const unsigned b[2]) {
    asm volatile(
        "mma.sync.aligned.m16n8k8.row.col.f32.tf32.tf32.f32 "
        "{%0,%1,%2,%3}, {%4,%5,%6,%7}, {%8,%9}, {%0,%1,%2,%3};\n"
        : "+f"(c[0]), "+f"(c[1]), "+f"(c[2]), "+f"(c[3])
        : "r"(a[0]), "r"(a[1]), "r"(a[2]), "r"(a[3]), "r"(b[0]), "r"(b[1]));
}

#define CP_ASYNC16(dst_u32, src) \
    asm volatile("cp.async.cg.shared.global [%0], [%1], 16;" :: "r"(dst_u32), "l"(src))
#define CP_COMMIT() asm volatile("cp.async.commit_group;")
#define CP_WAIT1()  asm volatile("cp.async.wait_group 1;")

// ---------------------------------------------------------------------------
// Prepass: round inputs + weights to tf32-valued floats in scratch.
// ---------------------------------------------------------------------------
__global__ __launch_bounds__(256) void round_tf32_kernel(
    const float* __restrict__ q, const float* __restrict__ k,
    const float* __restrict__ v, const float* __restrict__ wq,
    const float* __restrict__ wk, const float* __restrict__ wv,
    const float* __restrict__ wo)
{
    const int seg = blockIdx.y;
    const float* src;
    float* dst;
    int n;
    switch (seg) {
        case 0: src = q;  dst = g_Ain[0]; n = MROWS * DMODEL; break;
        case 1: src = k;  dst = g_Ain[1]; n = MROWS * DMODEL; break;
        case 2: src = v;  dst = g_Ain[2]; n = MROWS * DMODEL; break;
        case 3: src = wq; dst = g_Wt[0];  n = DMODEL * DMODEL; break;
        case 4: src = wk; dst = g_Wt[1];  n = DMODEL * DMODEL; break;
        case 5: src = wv; dst = g_Wt[2];  n = DMODEL * DMODEL; break;
        default: src = wo; dst = g_Wt[3]; n = DMODEL * DMODEL; break;
    }
    int idx = (blockIdx.x * 256 + threadIdx.x) << 2;
    if (idx < n) {
        float4 x = *(const float4*)&src[idx];
        float4 y;
        y.x = __uint_as_float(f2tf32(x.x));
        y.y = __uint_as_float(f2tf32(x.y));
        y.z = __uint_as_float(f2tf32(x.z));
        y.w = __uint_as_float(f2tf32(x.w));
        *(float4*)&dst[idx] = y;
    }
}

// ---------------------------------------------------------------------------
// Tensor-core GEMM core, plain tf32, cp.async double-buffered (R12 structure,
// the measured local optimum — at the legacy tensor 4cyc/mma ceiling).
// C[M,N] = A[M,K] @ W[N,K]^T.  M=4096, N=1024, K=1024.
// CTA 128x128, K-chunk 32 (4 k8 steps), 8 warps (4M x 2N), warp tile 32x64.
// smem row stride 36 words: fragment LDS bank = (4g+tg) mod 32, bijective.
// ---------------------------------------------------------------------------
#define GK 32
#define GTP 36
#define GBUF (128 * GTP)                       // words per matrix per buffer
#define GEMM_SMEM_BYTES (4 * GBUF * 4)         // A x2 + W x2 = 73728

__device__ __forceinline__ void gemm_issue_chunk(
    unsigned* Abuf, unsigned* Wbuf,
    const float* __restrict__ Ap, const float* __restrict__ W,
    int m0, int n0, int k0, int tid)
{
#pragma unroll
    for (int i = 0; i < 4; i++) {
        int f = tid + (i << 8);            // 0..1023
        int r = f >> 3;                    // 0..127
        int c4 = (f & 7) << 2;             // 0,4,..,28
        unsigned ad = (unsigned)__cvta_generic_to_shared(&Abuf[r * GTP + c4]);
        CP_ASYNC16(ad, &Ap[(m0 + r) * DMODEL + k0 + c4]);
        unsigned wd = (unsigned)__cvta_generic_to_shared(&Wbuf[r * GTP + c4]);
        CP_ASYNC16(wd, &W[(n0 + r) * DMODEL + k0 + c4]);
    }
}

__device__ __forceinline__ void gemm_core(
    const float* __restrict__ Ap, const float* __restrict__ W,
    int m0, int n0, float acc[2][8][4], unsigned* smem)
{
    unsigned* Abuf = smem;                 // [2][128][GTP]
    unsigned* Wbuf = smem + 2 * GBUF;

    const int tid  = threadIdx.x;
    const int warp = tid >> 5;
    const int lane = tid & 31;
    const int g    = lane >> 2;
    const int tg   = lane & 3;
    const int wm   = warp >> 1;
    const int wn   = warp & 1;

#pragma unroll
    for (int mf = 0; mf < 2; mf++)
#pragma unroll
        for (int nf = 0; nf < 8; nf++)
#pragma unroll
            for (int j = 0; j < 4; j++) acc[mf][nf][j] = 0.f;

    gemm_issue_chunk(Abuf, Wbuf, Ap, W, m0, n0, 0, tid);
    CP_COMMIT();

    const int NCHUNK = DMODEL / GK;        // 32
    for (int c = 0; c < NCHUNK; c++) {
        if (c > 0) __syncthreads();        // readers of the buffer we refill are done
        if (c + 1 < NCHUNK) {
            int nb = (c + 1) & 1;
            gemm_issue_chunk(Abuf + nb * GBUF, Wbuf + nb * GBUF,
                             Ap, W, m0, n0, (c + 1) * GK, tid);
        }
        CP_COMMIT();
        CP_WAIT1();
        __syncthreads();

        const unsigned* Ah = Abuf + (c & 1) * GBUF;
        const unsigned* Wh = Wbuf + (c & 1) * GBUF;

#pragma unroll
        for (int ks = 0; ks < 4; ks++) {
            const int kk = (ks << 3) + tg;
            unsigned ah[2][4];
#pragma unroll
            for (int mf = 0; mf < 2; mf++) {
                int r0 = (wm << 5) + (mf << 4) + g;
                ah[mf][0] = Ah[r0 * GTP + kk];       ah[mf][1] = Ah[(r0 + 8) * GTP + kk];
                ah[mf][2] = Ah[r0 * GTP + kk + 4];   ah[mf][3] = Ah[(r0 + 8) * GTP + kk + 4];
            }
#pragma unroll
            for (int nf = 0; nf < 8; nf++) {
                int nr = (wn << 6) + (nf << 3) + g;
                unsigned bh[2];
                bh[0] = Wh[nr * GTP + kk]; bh[1] = Wh[nr * GTP + kk + 4];
#pragma unroll
                for (int mf = 0; mf < 2; mf++) {
                    mma_tf32(acc[mf][nf], ah[mf], bh);
                }
            }
        }
    }
}

// ---- fused Q/K/V projections: blockIdx.z selects the GEMM.
// Q is additionally pre-scaled by QSCALE (softmax scale folded in). ----
__global__ __launch_bounds__(256, 2) void gemm_qkv_kernel()
{
    extern __shared__ unsigned gsm[];
    const int z = blockIdx.z;
    const float* Ap = g_Ain[z];
    const float* W  = g_Wt[z];
    float* outp     = (z == 0) ? g_Q : ((z == 1) ? g_K : g_V);
    const float sc  = (z == 0) ? QSCALE : 1.0f;

    const int m0 = blockIdx.y << 7;
    const int n0 = blockIdx.x << 7;

    float acc[2][8][4];
    gemm_core(Ap, W, m0, n0, acc, gsm);

    const int tid  = threadIdx.x;
    const int warp = tid >> 5;
    const int lane = tid & 31;
    const int g    = lane >> 2;
    const int tg   = lane & 3;
    const int wm   = warp >> 1;
    const int wn   = warp & 1;

#pragma unroll
    for (int mf = 0; mf < 2; mf++) {
        int m = m0 + (wm << 5) + (mf << 4) + g;
        int bb0 = m >> 11;
        int s   = m & 2047;
        int mb1 = m + 8;
        int bb1 = mb1 >> 11;
        int s1  = mb1 & 2047;
#pragma unroll
        for (int nf = 0; nf < 8; nf++) {
            int n = n0 + (wn << 6) + (nf << 3) + (tg << 1);
            int h = n >> 6;
            int d = n & 63;
            float2 w0, w1;
            w0.x = __uint_as_float(f2tf32(acc[mf][nf][0] * sc));
            w0.y = __uint_as_float(f2tf32(acc[mf][nf][1] * sc));
            w1.x = __uint_as_float(f2tf32(acc[mf][nf][2] * sc));
            w1.y = __uint_as_float(f2tf32(acc[mf][nf][3] * sc));
            *(float2*)&outp[(((bb0 << 4) + h) * SEQ + s) * DK + d] = w0;
            *(float2*)&outp[(((bb1 << 4) + h) * SEQ + s1) * DK + d] = w1;
        }
    }
}

// ---- output projection: C = g_O @ Wout^T + bias ----
__global__ __launch_bounds__(256, 2) void gemm_out_kernel(
    const float* __restrict__ bias, float* __restrict__ outFlat)
{
    extern __shared__ unsigned gsm[];
    const int m0 = blockIdx.y << 7;
    const int n0 = blockIdx.x << 7;

    float acc[2][8][4];
    gemm_core(g_O, g_Wt[3], m0, n0, acc, gsm);

    const int tid  = threadIdx.x;
    const int warp = tid >> 5;
    const int lane = tid & 31;
    const int g    = lane >> 2;
    const int tg   = lane & 3;
    const int wm   = warp >> 1;
    const int wn   = warp & 1;

#pragma unroll
    for (int mf = 0; mf < 2; mf++) {
        int r0 = m0 + (wm << 5) + (mf << 4) + g;
#pragma unroll
        for (int nf = 0; nf < 8; nf++) {
            int n = n0 + (wn << 6) + (nf << 3) + (tg << 1);
            float2 bi = *(const float2*)&bias[n];
            float2 w0, w1;
            w0.x = acc[mf][nf][0] + bi.x; w0.y = acc[mf][nf][1] + bi.y;
            w1.x = acc[mf][nf][2] + bi.x; w1.y = acc[mf][nf][3] + bi.y;
            *(float2*)&outFlat[r0 * DMODEL + n] = w0;
            *(float2*)&outFlat[(r0 + 8) * DMODEL + n] = w1;
        }
    }
}

// ---------------------------------------------------------------------------
// Flash attention, tf32 mma.sync, cp.async double-buffered K/V (R12 code).
// Balanced-pair schedule: bid 0..147 = heaviest ranks (one per SM),
// bid 148..295 = lightest ranks (paired on the same SMs -> each SM's
// resident pair sums to ~34 work units), bid 296..511 = middles heavy-first.
// ---------------------------------------------------------------------------
#define AQP_ST 72
#define AK_ST  68
#define AV_ST  72
#define KBUF_W (64 * AK_ST)
#define VBUF_W (64 * AV_ST)
#define ATTN_SMEM_BYTES ((128 * AQP_ST + 2 * KBUF_W + 2 * VBUF_W) * 4)  // 108544

__global__ __launch_bounds__(256, 2) void attn_mma_kernel(
    const unsigned char* __restrict__ mask, const int* __restrict__ is_causal_p)
{
    extern __shared__ unsigned smu[];
    unsigned* QPs  = smu;                       // [128][72]
    unsigned* Kbuf = smu + 128 * AQP_ST;        // 2 x [64][68]
    unsigned* Vbuf = Kbuf + 2 * KBUF_W;         // 2 x [64][72]

    const int bid = blockIdx.x;                 // 0..511
    int rank;
    if (bid < 148)      rank = bid;                    // heaviest, 1 per SM
    else if (bid < 296) rank = 511 - (bid - 148);      // lightest, pair up
    else                rank = 148 + (bid - 296);      // middles, heavy-first
    const int qt = (SEQ / 128 - 1) - (rank >> 5);      // rank 0 -> qt=15
    const int bh = rank & 31;
    const int b  = bh >> 4;
    const int h  = bh & 15;
    const int causal = is_causal_p[0];
    const int q0 = qt << 7;

    const int tid  = threadIdx.x;
    const int warp = tid >> 5;
    const int lane = tid & 31;
    const int g    = lane >> 2;
    const int tg   = lane & 3;

    const float* Qg = g_Q + ((size_t)bh * SEQ + q0) * DK;
    const float* Kg = g_K + (size_t)bh * SEQ * DK;
    const float* Vg = g_V + (size_t)bh * SEQ * DK;

    const int lrow = tid >> 4;              // 0..15
    const int lc4  = (tid & 15) << 2;       // 0,4,..,60

    // ---- Load Q tile (already tf32-valued + pre-scaled): plain copy ----
#pragma unroll
    for (int it = 0; it < 8; it++) {
        int r = lrow + (it << 4);
        *(uint4*)&QPs[r * AQP_ST + lc4] = *(const uint4*)&Qg[r * DK + lc4];
    }

    // ---- cp.async tile 0 into buffer 0 ----
#pragma unroll
    for (int it = 0; it < 4; it++) {
        int r = lrow + (it << 4);
        unsigned kd = (unsigned)__cvta_generic_to_shared(&Kbuf[r * AK_ST + lc4]);
        CP_ASYNC16(kd, &Kg[r * DK + lc4]);
        unsigned vd = (unsigned)__cvta_generic_to_shared(&Vbuf[r * AV_ST + lc4]);
        CP_ASYNC16(vd, &Vg[r * DK + lc4]);
    }
    CP_COMMIT();
    __syncthreads();

    // ---- Q fragments ----
    const int r0 = (warp << 4) + g;
    const int r1 = r0 + 8;
    unsigned qf[8][4];
#pragma unroll
    for (int ks = 0; ks < 8; ks++) {
        int k = (ks << 3) + tg;
        qf[ks][0] = QPs[r0 * AQP_ST + k];
        qf[ks][1] = QPs[r1 * AQP_ST + k];
        qf[ks][2] = QPs[r0 * AQP_ST + k + 4];
        qf[ks][3] = QPs[r1 * AQP_ST + k + 4];
    }

    const int gr0 = q0 + r0;
    const int gr1 = q0 + r1;
    const unsigned char* mrow0 = mask + (size_t)b * SEQ * SEQ + (size_t)gr0 * SEQ;
    const unsigned char* mrow1 = mask + (size_t)b * SEQ * SEQ + (size_t)gr1 * SEQ;

    float m0 = -1e30f, m1 = -1e30f, l0 = 0.f, l1 = 0.f;
    float of[8][4];
#pragma unroll
    for (int nf = 0; nf < 8; nf++)
#pragma unroll
        for (int j = 0; j < 4; j++) of[nf][j] = 0.f;

    const int ntiles = causal ? (2 * qt + 2) : (SEQ / 64);

    for (int t = 0; t < ntiles; t++) {
        const int k0 = t << 6;
        if (t > 0) __syncthreads();

        if (t + 1 < ntiles) {
            const int nb = (t + 1) & 1;
            const float* Kt = Kg + ((t + 1) << 6) * DK;
            const float* Vt = Vg + ((t + 1) << 6) * DK;
            unsigned* Kd = Kbuf + nb * KBUF_W;
            unsigned* Vd = Vbuf + nb * VBUF_W;
#pragma unroll
            for (int it = 0; it < 4; it++) {
                int r = lrow + (it << 4);
                unsigned kd = (unsigned)__cvta_generic_to_shared(&Kd[r * AK_ST + lc4]);
                CP_ASYNC16(kd, &Kt[r * DK + lc4]);
                unsigned vd = (unsigned)__cvta_generic_to_shared(&Vd[r * AV_ST + lc4]);
                CP_ASYNC16(vd, &Vt[r * DK + lc4]);
            }
        }
        CP_COMMIT();
        CP_WAIT1();
        __syncthreads();

        const unsigned* Kb = Kbuf + (t & 1) * KBUF_W;
        const unsigned* Vb = Vbuf + (t & 1) * VBUF_W;

        // ---- mask prefetch ----
        uchar2 mA[8], mB[8];
#pragma unroll
        for (int nf = 0; nf < 8; nf++) {
            int col = k0 + (nf << 3) + (tg << 1);
            mA[nf] = *(const uchar2*)(mrow0 + col);
            mB[nf] = *(const uchar2*)(mrow1 + col);
        }

        // ---- S = Q @ K^T (scores already in log2 domain) ----
        float s[8][4];
#pragma unroll
        for (int nf = 0; nf < 8; nf++)
#pragma unroll
            for (int j = 0; j < 4; j++) s[nf][j] = 0.f;

#pragma unroll
        for (int nf = 0; nf < 8; nf++) {
            int nrow = (nf << 3) + g;
#pragma unroll
            for (int ks = 0; ks < 8; ks++) {
                int k = (ks << 3) + tg;
                unsigned bb[2];
                bb[0] = Kb[nrow * AK_ST + k];
                bb[1] = Kb[nrow * AK_ST + k + 4];
                mma_tf32(s[nf], qf[ks], bb);
            }
        }

        // ---- mask (no scale multiply needed) ----
#pragma unroll
        for (int nf = 0; nf < 8; nf++) {
            int col = k0 + (nf << 3) + (tg << 1);
            bool d00 = mA[nf].x || (causal && (col     > gr0));
            bool d01 = mA[nf].y || (causal && (col + 1 > gr0));
            bool d10 = mB[nf].x || (causal && (col     > gr1));
            bool d11 = mB[nf].y || (causal && (col + 1 > gr1));
            if (d00) s[nf][0] = -1e30f;
            if (d01) s[nf][1] = -1e30f;
            if (d10) s[nf][2] = -1e30f;
            if (d11) s[nf][3] = -1e30f;
        }

        // ---- online softmax in base-2 ----
        float mx0 = -1e30f, mx1 = -1e30f;
#pragma unroll
        for (int nf = 0; nf < 8; nf++) {
            mx0 = fmaxf(mx0, fmaxf(s[nf][0], s[nf][1]));
            mx1 = fmaxf(mx1, fmaxf(s[nf][2], s[nf][3]));
        }
        mx0 = fmaxf(mx0, __shfl_xor_sync(0xffffffffu, mx0, 1));
        mx0 = fmaxf(mx0, __shfl_xor_sync(0xffffffffu, mx0, 2));
        mx1 = fmaxf(mx1, __shfl_xor_sync(0xffffffffu, mx1, 1));
        mx1 = fmaxf(mx1, __shfl_xor_sync(0xffffffffu, mx1, 2));
        float m0n = fmaxf(m0, mx0);
        float m1n = fmaxf(m1, mx1);
        float sf0 = ex2f(m0 - m0n);
        float sf1 = ex2f(m1 - m1n);
        float rs0 = 0.f, rs1 = 0.f;
#pragma unroll
        for (int nf = 0; nf < 8; nf++) {
            float p0 = ex2f(s[nf][0] - m0n);
            float p1 = ex2f(s[nf][1] - m0n);
            float p2 = ex2f(s[nf][2] - m1n);
            float p3 = ex2f(s[nf][3] - m1n);
            s[nf][0] = p0; s[nf][1] = p1; s[nf][2] = p2; s[nf][3] = p3;
            rs0 += p0 + p1;
            rs1 += p2 + p3;
        }
        rs0 += __shfl_xor_sync(0xffffffffu, rs0, 1);
        rs0 += __shfl_xor_sync(0xffffffffu, rs0, 2);
        rs1 += __shfl_xor_sync(0xffffffffu, rs1, 1);
        rs1 += __shfl_xor_sync(0xffffffffu, rs1, 2);
        l0 = l0 * sf0 + rs0;
        l1 = l1 * sf1 + rs1;
        m0 = m0n; m1 = m1n;
#pragma unroll
        for (int nf = 0; nf < 8; nf++) {
            of[nf][0] *= sf0; of[nf][1] *= sf0;
            of[nf][2] *= sf1; of[nf][3] *= sf1;
        }

        // ---- write P (tf32) to warp-local rows of QPs ----
#pragma unroll
        for (int nf = 0; nf < 8; nf++) {
            int c = (nf << 3) + (tg << 1);
            uint2 p0; p0.x = f2tf32(s[nf][0]); p0.y = f2tf32(s[nf][1]);
            uint2 p1; p1.x = f2tf32(s[nf][2]); p1.y = f2tf32(s[nf][3]);
            *(uint2*)&QPs[r0 * AQP_ST + c] = p0;
            *(uint2*)&QPs[r1 * AQP_ST + c] = p1;
        }
        __syncwarp();

        // ---- O += P @ V ----
#pragma unroll
        for (int ks = 0; ks < 8; ks++) {
            unsigned a[4];
            int k = (ks << 3) + tg;
            a[0] = QPs[r0 * AQP_ST + k];
            a[1] = QPs[r1 * AQP_ST + k];
            a[2] = QPs[r0 * AQP_ST + k + 4];
            a[3] = QPs[r1 * AQP_ST + k + 4];
#pragma unroll
            for (int nf = 0; nf < 8; nf++) {
                int n = (nf << 3) + g;
                unsigned bb[2];
                bb[0] = Vb[((ks << 3) + tg) * AV_ST + n];
                bb[1] = Vb[((ks << 3) + tg + 4) * AV_ST + n];
                mma_tf32(of[nf], a, bb);
            }
        }
        __syncwarp();
    }

    // ---- epilogue: normalize + round to tf32 for the out-projection ----
    float inv0 = (m0 > -1e29f && l0 > 0.f) ? (1.f / l0) : 0.f;
    float inv1 = (m1 > -1e29f && l1 > 0.f) ? (1.f / l1) : 0.f;
    float* Og0 = g_O + ((size_t)b * SEQ + gr0) * DMODEL + (h << 6);
    float* Og1 = g_O + ((size_t)b * SEQ + gr1) * DMODEL + (h << 6);
#pragma unroll
    for (int nf = 0; nf < 8; nf++) {
        int c = (nf << 3) + (tg << 1);
        float2 w0, w1;
        w0.x = __uint_as_float(f2tf32(of[nf][0] * inv0));
        w0.y = __uint_as_float(f2tf32(of[nf][1] * inv0));
        w1.x = __uint_as_float(f2tf32(of[nf][2] * inv1));
        w1.y = __uint_as_float(f2tf32(of[nf][3] * inv1));
        *(float2*)&Og0[c] = w0;
        *(float2*)&Og1[c] = w1;
    }
}

// ---------------------------------------------------------------------------
extern "C" void kernel_launch(void* const* d_in, const int* in_sizes, int n_in,
                              void* d_out, int out_size)
{
    const float* query = (const float*)d_in[0];
    const float* key   = (const float*)d_in[1];
    const float* value = (const float*)d_in[2];
    const unsigned char* mask = (const unsigned char*)d_in[3];
    const float* Wq    = (const float*)d_in[4];
    const float* Wk    = (const float*)d_in[5];
    const float* Wv    = (const float*)d_in[6];
    const float* Wout  = (const float*)d_in[7];
    const float* b_out = (const float*)d_in[8];
    const int* is_causal = (const int*)d_in[9];
    float* out = (float*)d_out;

    cudaFuncSetAttribute(attn_mma_kernel,
                         cudaFuncAttributeMaxDynamicSharedMemorySize, ATTN_SMEM_BYTES);
    cudaFuncSetAttribute(gemm_qkv_kernel,
                         cudaFuncAttributeMaxDynamicSharedMemorySize, GEMM_SMEM_BYTES);
    cudaFuncSetAttribute(gemm_out_kernel,
                         cudaFuncAttributeMaxDynamicSharedMemorySize, GEMM_SMEM_BYTES);

    // prepass: round inputs + weights to tf32 in scratch
    dim3 rgrid((MROWS * DMODEL / 4 + 255) / 256, 7);   // (4096, 7)
    round_tf32_kernel<<<rgrid, 256>>>(query, key, value, Wq, Wk, Wv, Wout);

    dim3 qkvgrid(DMODEL / 128, MROWS / 128, 3);   // (8, 32, 3)
    gemm_qkv_kernel<<<qkvgrid, 256, GEMM_SMEM_BYTES>>>();

    // attention: 1D grid, balanced heavy+light pairing per SM
    attn_mma_kernel<<<(SEQ / 128) * BATCH * NHEAD, 256, ATTN_SMEM_BYTES>>>(mask, is_causal);

    dim3 ogrid(DMODEL / 128, MROWS / 128);        // (8, 32)
    gemm_out_kernel<<<ogrid, 256, GEMM_SMEM_BYTES>>>(b_out, out);
}

// round 17
// speedup vs baseline: 1.3638x; 1.3638x over previous
#include <cuda_runtime.h>
#include <cuda_fp16.h>
#include <cstdint>

// Problem constants (fixed by the reference setup_inputs)
#define BATCH 2
#define SEQ   2048
#define DMODEL 1024
#define NHEAD 16
#define DK    64
#define MROWS (BATCH * SEQ)   // 4096

// Q is pre-scaled by 1/sqrt(dk) * log2(e) at the projection epilogue, so the
// attention softmax runs natively in base-2 (single MUFU per score).
#define QSCALE 0.18033688011112042f   // 0.125 * log2(e)

// Scratch
__device__ float  g_Q[BATCH * NHEAD * SEQ * DK];   // tf32-valued
__device__ float  g_K[BATCH * NHEAD * SEQ * DK];   // tf32-valued
__device__ float  g_V[BATCH * NHEAD * SEQ * DK];   // tf32-valued
__device__ __half g_O[BATCH * SEQ * DMODEL];       // fp16 (attn epilogue rounds)
__device__ __half g_Ain[3][MROWS * DMODEL];        // fp16 query/key/value
__device__ __half g_Wt[4][DMODEL * DMODEL];        // fp16 Wq/Wk/Wv/Wout

// ---------------------------------------------------------------------------
// helpers
// ---------------------------------------------------------------------------
__device__ __forceinline__ unsigned f2tf32(float f) {
    unsigned u;
    asm("cvt.rna.tf32.f32 %0, %1;" : "=r"(u) : "f"(f));
    return u;
}

__device__ __forceinline__ float ex2f(float x) {
    float r;
    asm("ex2.approx.f32 %0, %1;" : "=f"(r) : "f"(x));
    return r;
}

__device__ __forceinline__ void mma_tf32(float c[4], const unsigned a[4], const unsigned b[2]) {
    asm volatile(
        "mma.sync.aligned.m16n8k8.row.col.f32.tf32.tf32.f32 "
        "{%0,%1,%2,%3}, {%4,%5,%6,%7}, {%8,%9}, {%0,%1,%2,%3};\n"
        : "+f"(c[0]), "+f"(c[1]), "+f"(c[2]), "+f"(c[3])
        : "r"(a[0]), "r"(a[1]), "r"(a[2]), "r"(a[3]), "r"(b[0]), "r"(b[1]));
}

__device__ __forceinline__ void mma_f16(float c[4], const unsigned a[4], const unsigned b[2]) {
    asm volatile(
        "mma.sync.aligned.m16n8k16.row.col.f32.f16.f16.f32 "
        "{%0,%1,%2,%3}, {%4,%5,%6,%7}, {%8,%9}, {%0,%1,%2,%3};\n"
        : "+f"(c[0]), "+f"(c[1]), "+f"(c[2]), "+f"(c[3])
        : "r"(a[0]), "r"(a[1]), "r"(a[2]), "r"(a[3]), "r"(b[0]), "r"(b[1]));
}

#define CP_ASYNC16(dst_u32, src) \
    asm volatile("cp.async.cg.shared.global [%0], [%1], 16;" :: "r"(dst_u32), "l"(src))
#define CP_COMMIT() asm volatile("cp.async.commit_group;")
#define CP_WAIT1()  asm volatile("cp.async.wait_group 1;")

// ---------------------------------------------------------------------------
// Prepass: round inputs + weights to fp16 in scratch.
// ---------------------------------------------------------------------------
__global__ __launch_bounds__(256) void round_f16_kernel(
    const float* __restrict__ q, const float* __restrict__ k,
    const float* __restrict__ v, const float* __restrict__ wq,
    const float* __restrict__ wk, const float* __restrict__ wv,
    const float* __restrict__ wo)
{
    const int seg = blockIdx.y;
    const float* src;
    __half* dst;
    int n;
    switch (seg) {
        case 0: src = q;  dst = g_Ain[0]; n = MROWS * DMODEL; break;
        case 1: src = k;  dst = g_Ain[1]; n = MROWS * DMODEL; break;
        case 2: src = v;  dst = g_Ain[2]; n = MROWS * DMODEL; break;
        case 3: src = wq; dst = g_Wt[0];  n = DMODEL * DMODEL; break;
        case 4: src = wk; dst = g_Wt[1];  n = DMODEL * DMODEL; break;
        case 5: src = wv; dst = g_Wt[2];  n = DMODEL * DMODEL; break;
        default: src = wo; dst = g_Wt[3]; n = DMODEL * DMODEL; break;
    }
    int idx = (blockIdx.x * 256 + threadIdx.x) << 2;
    if (idx < n) {
        float4 x = *(const float4*)&src[idx];
        __half2 h0 = __floats2half2_rn(x.x, x.y);
        __half2 h1 = __floats2half2_rn(x.z, x.w);
        *(__half2*)&dst[idx]     = h0;
        *(__half2*)&dst[idx + 2] = h1;
    }
}

// ---------------------------------------------------------------------------
// Tensor-core GEMM core, fp16 (m16n8k16, f32 accum), cp.async double-buffered.
// Same structure/addressing as the proven tf32 R12 core — word-level index
// math is identical; each 32-bit smem word now holds 2 fp16 values so the
// K-chunk covers 64 elements with the SAME byte footprint.
// C[M,N] = A[M,K] @ W[N,K]^T.  M=4096, N=1024, K=1024.
// CTA 128x128, K-chunk 64 (4 k16 steps), 8 warps (4M x 2N), warp tile 32x64.
// smem row stride 36 words: fragment LDS bank = (4g+tg) mod 32, bijective.
// ---------------------------------------------------------------------------
#define GK 64
#define GTP 36
#define GBUF (128 * GTP)                       // words per matrix per buffer
#define GEMM_SMEM_BYTES (4 * GBUF * 4)         // A x2 + W x2 = 73728

__device__ __forceinline__ void gemm_issue_chunk(
    unsigned* Abuf, unsigned* Wbuf,
    const __half* __restrict__ Ap, const __half* __restrict__ W,
    int m0, int n0, int k0, int tid)
{
#pragma unroll
    for (int i = 0; i < 4; i++) {
        int f = tid + (i << 8);            // 0..1023
        int r = f >> 3;                    // 0..127
        int c4 = (f & 7) << 2;             // word offset 0,4,..,28
        int ch = (f & 7) << 3;             // half offset 0,8,..,56
        unsigned ad = (unsigned)__cvta_generic_to_shared(&Abuf[r * GTP + c4]);
        CP_ASYNC16(ad, &Ap[(m0 + r) * DMODEL + k0 + ch]);
        unsigned wd = (unsigned)__cvta_generic_to_shared(&Wbuf[r * GTP + c4]);
        CP_ASYNC16(wd, &W[(n0 + r) * DMODEL + k0 + ch]);
    }
}

__device__ __forceinline__ void gemm_core(
    const __half* __restrict__ Ap, const __half* __restrict__ W,
    int m0, int n0, float acc[2][8][4], unsigned* smem)
{
    unsigned* Abuf = smem;                 // [2][128][GTP]
    unsigned* Wbuf = smem + 2 * GBUF;

    const int tid  = threadIdx.x;
    const int warp = tid >> 5;
    const int lane = tid & 31;
    const int g    = lane >> 2;
    const int tg   = lane & 3;
    const int wm   = warp >> 1;
    const int wn   = warp & 1;

#pragma unroll
    for (int mf = 0; mf < 2; mf++)
#pragma unroll
        for (int nf = 0; nf < 8; nf++)
#pragma unroll
            for (int j = 0; j < 4; j++) acc[mf][nf][j] = 0.f;

    gemm_issue_chunk(Abuf, Wbuf, Ap, W, m0, n0, 0, tid);
    CP_COMMIT();

    const int NCHUNK = DMODEL / GK;        // 16
    for (int c = 0; c < NCHUNK; c++) {
        if (c > 0) __syncthreads();        // readers of the buffer we refill are done
        if (c + 1 < NCHUNK) {
            int nb = (c + 1) & 1;
            gemm_issue_chunk(Abuf + nb * GBUF, Wbuf + nb * GBUF,
                             Ap, W, m0, n0, (c + 1) * GK, tid);
        }
        CP_COMMIT();
        CP_WAIT1();
        __syncthreads();

        const unsigned* Ah = Abuf + (c & 1) * GBUF;
        const unsigned* Wh = Wbuf + (c & 1) * GBUF;

#pragma unroll
        for (int ks = 0; ks < 4; ks++) {
            const int kk = (ks << 3) + tg;
            unsigned ah[2][4];
#pragma unroll
            for (int mf = 0; mf < 2; mf++) {
                int r0 = (wm << 5) + (mf << 4) + g;
                ah[mf][0] = Ah[r0 * GTP + kk];       ah[mf][1] = Ah[(r0 + 8) * GTP + kk];
                ah[mf][2] = Ah[r0 * GTP + kk + 4];   ah[mf][3] = Ah[(r0 + 8) * GTP + kk + 4];
            }
#pragma unroll
            for (int nf = 0; nf < 8; nf++) {
                int nr = (wn << 6) + (nf << 3) + g;
                unsigned bh[2];
                bh[0] = Wh[nr * GTP + kk]; bh[1] = Wh[nr * GTP + kk + 4];
#pragma unroll
                for (int mf = 0; mf < 2; mf++) {
                    mma_f16(acc[mf][nf], ah[mf], bh);
                }
            }
        }
    }
}

// ---- fused Q/K/V projections: blockIdx.z selects the GEMM.
// Q is additionally pre-scaled by QSCALE (softmax scale folded in).
// Outputs rounded to tf32-valued fp32 so the attention kernel needs NO cvt. ----
__global__ __launch_bounds__(256, 2) void gemm_qkv_kernel()
{
    extern __shared__ unsigned gsm[];
    const int z = blockIdx.z;
    const __half* Ap = g_Ain[z];
    const __half* W  = g_Wt[z];
    float* outp      = (z == 0) ? g_Q : ((z == 1) ? g_K : g_V);
    const float sc   = (z == 0) ? QSCALE : 1.0f;

    const int m0 = blockIdx.y << 7;
    const int n0 = blockIdx.x << 7;

    float acc[2][8][4];
    gemm_core(Ap, W, m0, n0, acc, gsm);

    const int tid  = threadIdx.x;
    const int warp = tid >> 5;
    const int lane = tid & 31;
    const int g    = lane >> 2;
    const int tg   = lane & 3;
    const int wm   = warp >> 1;
    const int wn   = warp & 1;

#pragma unroll
    for (int mf = 0; mf < 2; mf++) {
        int m = m0 + (wm << 5) + (mf << 4) + g;
        int bb0 = m >> 11;
        int s   = m & 2047;
        int mb1 = m + 8;
        int bb1 = mb1 >> 11;
        int s1  = mb1 & 2047;
#pragma unroll
        for (int nf = 0; nf < 8; nf++) {
            int n = n0 + (wn << 6) + (nf << 3) + (tg << 1);
            int h = n >> 6;
            int d = n & 63;
            float2 w0, w1;
            w0.x = __uint_as_float(f2tf32(acc[mf][nf][0] * sc));
            w0.y = __uint_as_float(f2tf32(acc[mf][nf][1] * sc));
            w1.x = __uint_as_float(f2tf32(acc[mf][nf][2] * sc));
            w1.y = __uint_as_float(f2tf32(acc[mf][nf][3] * sc));
            *(float2*)&outp[(((bb0 << 4) + h) * SEQ + s) * DK + d] = w0;
            *(float2*)&outp[(((bb1 << 4) + h) * SEQ + s1) * DK + d] = w1;
        }
    }
}

// ---- output projection: C = g_O @ Wout^T + bias ----
__global__ __launch_bounds__(256, 2) void gemm_out_kernel(
    const float* __restrict__ bias, float* __restrict__ outFlat)
{
    extern __shared__ unsigned gsm[];
    const int m0 = blockIdx.y << 7;
    const int n0 = blockIdx.x << 7;

    float acc[2][8][4];
    gemm_core(g_O, g_Wt[3], m0, n0, acc, gsm);

    const int tid  = threadIdx.x;
    const int warp = tid >> 5;
    const int lane = tid & 31;
    const int g    = lane >> 2;
    const int tg   = lane & 3;
    const int wm   = warp >> 1;
    const int wn   = warp & 1;

#pragma unroll
    for (int mf = 0; mf < 2; mf++) {
        int r0 = m0 + (wm << 5) + (mf << 4) + g;
#pragma unroll
        for (int nf = 0; nf < 8; nf++) {
            int n = n0 + (wn << 6) + (nf << 3) + (tg << 1);
            float2 bi = *(const float2*)&bias[n];
            float2 w0, w1;
            w0.x = acc[mf][nf][0] + bi.x; w0.y = acc[mf][nf][1] + bi.y;
            w1.x = acc[mf][nf][2] + bi.x; w1.y = acc[mf][nf][3] + bi.y;
            *(float2*)&outFlat[r0 * DMODEL + n] = w0;
            *(float2*)&outFlat[(r0 + 8) * DMODEL + n] = w1;
        }
    }
}

// ---------------------------------------------------------------------------
// Flash attention, tf32 mma.sync, cp.async double-buffered K/V (R15 code —
// heavy-first schedule). Only the epilogue changed: writes g_O as fp16.
// ---------------------------------------------------------------------------
#define AQP_ST 72
#define AK_ST  68
#define AV_ST  72
#define KBUF_W (64 * AK_ST)
#define VBUF_W (64 * AV_ST)
#define ATTN_SMEM_BYTES ((128 * AQP_ST + 2 * KBUF_W + 2 * VBUF_W) * 4)  // 108544

__global__ __launch_bounds__(256, 2) void attn_mma_kernel(
    const unsigned char* __restrict__ mask, const int* __restrict__ is_causal_p)
{
    extern __shared__ unsigned smu[];
    unsigned* QPs  = smu;                       // [128][72]
    unsigned* Kbuf = smu + 128 * AQP_ST;        // 2 x [64][68]
    unsigned* Vbuf = Kbuf + 2 * KBUF_W;         // 2 x [64][72]

    const int bid = blockIdx.x;                 // 0..511
    const int qt  = (SEQ / 128 - 1) - (bid >> 5);  // heavy (qt=15) first
    const int bh  = bid & 31;
    const int b   = bh >> 4;
    const int h   = bh & 15;
    const int causal = is_causal_p[0];
    const int q0 = qt << 7;

    const int tid  = threadIdx.x;
    const int warp = tid >> 5;
    const int lane = tid & 31;
    const int g    = lane >> 2;
    const int tg   = lane & 3;

    const float* Qg = g_Q + ((size_t)bh * SEQ + q0) * DK;
    const float* Kg = g_K + (size_t)bh * SEQ * DK;
    const float* Vg = g_V + (size_t)bh * SEQ * DK;

    const int lrow = tid >> 4;              // 0..15
    const int lc4  = (tid & 15) << 2;       // 0,4,..,60

    // ---- Load Q tile (already tf32-valued + pre-scaled): plain copy ----
#pragma unroll
    for (int it = 0; it < 8; it++) {
        int r = lrow + (it << 4);
        *(uint4*)&QPs[r * AQP_ST + lc4] = *(const uint4*)&Qg[r * DK + lc4];
    }

    // ---- cp.async tile 0 into buffer 0 ----
#pragma unroll
    for (int it = 0; it < 4; it++) {
        int r = lrow + (it << 4);
        unsigned kd = (unsigned)__cvta_generic_to_shared(&Kbuf[r * AK_ST + lc4]);
        CP_ASYNC16(kd, &Kg[r * DK + lc4]);
        unsigned vd = (unsigned)__cvta_generic_to_shared(&Vbuf[r * AV_ST + lc4]);
        CP_ASYNC16(vd, &Vg[r * DK + lc4]);
    }
    CP_COMMIT();
    __syncthreads();

    // ---- Q fragments ----
    const int r0 = (warp << 4) + g;
    const int r1 = r0 + 8;
    unsigned qf[8][4];
#pragma unroll
    for (int ks = 0; ks < 8; ks++) {
        int k = (ks << 3) + tg;
        qf[ks][0] = QPs[r0 * AQP_ST + k];
        qf[ks][1] = QPs[r1 * AQP_ST + k];
        qf[ks][2] = QPs[r0 * AQP_ST + k + 4];
        qf[ks][3] = QPs[r1 * AQP_ST + k + 4];
    }

    const int gr0 = q0 + r0;
    const int gr1 = q0 + r1;
    const unsigned char* mrow0 = mask + (size_t)b * SEQ * SEQ + (size_t)gr0 * SEQ;
    const unsigned char* mrow1 = mask + (size_t)b * SEQ * SEQ + (size_t)gr1 * SEQ;

    float m0 = -1e30f, m1 = -1e30f, l0 = 0.f, l1 = 0.f;
    float of[8][4];
#pragma unroll
    for (int nf = 0; nf < 8; nf++)
#pragma unroll
        for (int j = 0; j < 4; j++) of[nf][j] = 0.f;

    const int ntiles = causal ? (2 * qt + 2) : (SEQ / 64);

    for (int t = 0; t < ntiles; t++) {
        const int k0 = t << 6;
        if (t > 0) __syncthreads();

        if (t + 1 < ntiles) {
            const int nb = (t + 1) & 1;
            const float* Kt = Kg + ((t + 1) << 6) * DK;
            const float* Vt = Vg + ((t + 1) << 6) * DK;
            unsigned* Kd = Kbuf + nb * KBUF_W;
            unsigned* Vd = Vbuf + nb * VBUF_W;
#pragma unroll
            for (int it = 0; it < 4; it++) {
                int r = lrow + (it << 4);
                unsigned kd = (unsigned)__cvta_generic_to_shared(&Kd[r * AK_ST + lc4]);
                CP_ASYNC16(kd, &Kt[r * DK + lc4]);
                unsigned vd = (unsigned)__cvta_generic_to_shared(&Vd[r * AV_ST + lc4]);
                CP_ASYNC16(vd, &Vt[r * DK + lc4]);
            }
        }
        CP_COMMIT();
        CP_WAIT1();
        __syncthreads();

        const unsigned* Kb = Kbuf + (t & 1) * KBUF_W;
        const unsigned* Vb = Vbuf + (t & 1) * VBUF_W;

        // ---- mask prefetch ----
        uchar2 mA[8], mB[8];
#pragma unroll
        for (int nf = 0; nf < 8; nf++) {
            int col = k0 + (nf << 3) + (tg << 1);
            mA[nf] = *(const uchar2*)(mrow0 + col);
            mB[nf] = *(const uchar2*)(mrow1 + col);
        }

        // ---- S = Q @ K^T (scores already in log2 domain) ----
        float s[8][4];
#pragma unroll
        for (int nf = 0; nf < 8; nf++)
#pragma unroll
            for (int j = 0; j < 4; j++) s[nf][j] = 0.f;

#pragma unroll
        for (int nf = 0; nf < 8; nf++) {
            int nrow = (nf << 3) + g;
#pragma unroll
            for (int ks = 0; ks < 8; ks++) {
                int k = (ks << 3) + tg;
                unsigned bb[2];
                bb[0] = Kb[nrow * AK_ST + k];
                bb[1] = Kb[nrow * AK_ST + k + 4];
                mma_tf32(s[nf], qf[ks], bb);
            }
        }

        // ---- mask (no scale multiply needed) ----
#pragma unroll
        for (int nf = 0; nf < 8; nf++) {
            int col = k0 + (nf << 3) + (tg << 1);
            bool d00 = mA[nf].x || (causal && (col     > gr0));
            bool d01 = mA[nf].y || (causal && (col + 1 > gr0));
            bool d10 = mB[nf].x || (causal && (col     > gr1));
            bool d11 = mB[nf].y || (causal && (col + 1 > gr1));
            if (d00) s[nf][0] = -1e30f;
            if (d01) s[nf][1] = -1e30f;
            if (d10) s[nf][2] = -1e30f;
            if (d11) s[nf][3] = -1e30f;
        }

        // ---- online softmax in base-2 ----
        float mx0 = -1e30f, mx1 = -1e30f;
#pragma unroll
        for (int nf = 0; nf < 8; nf++) {
            mx0 = fmaxf(mx0, fmaxf(s[nf][0], s[nf][1]));
            mx1 = fmaxf(mx1, fmaxf(s[nf][2], s[nf][3]));
        }
        mx0 = fmaxf(mx0, __shfl_xor_sync(0xffffffffu, mx0, 1));
        mx0 = fmaxf(mx0, __shfl_xor_sync(0xffffffffu, mx0, 2));
        mx1 = fmaxf(mx1, __shfl_xor_sync(0xffffffffu, mx1, 1));
        mx1 = fmaxf(mx1, __shfl_xor_sync(0xffffffffu, mx1, 2));
        float m0n = fmaxf(m0, mx0);
        float m1n = fmaxf(m1, mx1);
        float sf0 = ex2f(m0 - m0n);
        float sf1 = ex2f(m1 - m1n);
        float rs0 = 0.f, rs1 = 0.f;
#pragma unroll
        for (int nf = 0; nf < 8; nf++) {
            float p0 = ex2f(s[nf][0] - m0n);
            float p1 = ex2f(s[nf][1] - m0n);
            float p2 = ex2f(s[nf][2] - m1n);
            float p3 = ex2f(s[nf][3] - m1n);
            s[nf][0] = p0; s[nf][1] = p1; s[nf][2] = p2; s[nf][3] = p3;
            rs0 += p0 + p1;
            rs1 += p2 + p3;
        }
        rs0 += __shfl_xor_sync(0xffffffffu, rs0, 1);
        rs0 += __shfl_xor_sync(0xffffffffu, rs0, 2);
        rs1 += __shfl_xor_sync(0xffffffffu, rs1, 1);
        rs1 += __shfl_xor_sync(0xffffffffu, rs1, 2);
        l0 = l0 * sf0 + rs0;
        l1 = l1 * sf1 + rs1;
        m0 = m0n; m1 = m1n;
#pragma unroll
        for (int nf = 0; nf < 8; nf++) {
            of[nf][0] *= sf0; of[nf][1] *= sf0;
            of[nf][2] *= sf1; of[nf][3] *= sf1;
        }

        // ---- write P (tf32) to warp-local rows of QPs ----
#pragma unroll
        for (int nf = 0; nf < 8; nf++) {
            int c = (nf << 3) + (tg << 1);
            uint2 p0; p0.x = f2tf32(s[nf][0]); p0.y = f2tf32(s[nf][1]);
            uint2 p1; p1.x = f2tf32(s[nf][2]); p1.y = f2tf32(s[nf][3]);
            *(uint2*)&QPs[r0 * AQP_ST + c] = p0;
            *(uint2*)&QPs[r1 * AQP_ST + c] = p1;
        }
        __syncwarp();

        // ---- O += P @ V ----
#pragma unroll
        for (int ks = 0; ks < 8; ks++) {
            unsigned a[4];
            int k = (ks << 3) + tg;
            a[0] = QPs[r0 * AQP_ST + k];
            a[1] = QPs[r1 * AQP_ST + k];
            a[2] = QPs[r0 * AQP_ST + k + 4];
            a[3] = QPs[r1 * AQP_ST + k + 4];
#pragma unroll
            for (int nf = 0; nf < 8; nf++) {
                int n = (nf << 3) + g;
                unsigned bb[2];
                bb[0] = Vb[((ks << 3) + tg) * AV_ST + n];
                bb[1] = Vb[((ks << 3) + tg + 4) * AV_ST + n];
                mma_tf32(of[nf], a, bb);
            }
        }
        __syncwarp();
    }

    // ---- epilogue: normalize + round to fp16 for the out-projection ----
    float inv0 = (m0 > -1e29f && l0 > 0.f) ? (1.f / l0) : 0.f;
    float inv1 = (m1 > -1e29f && l1 > 0.f) ? (1.f / l1) : 0.f;
    __half* Og0 = g_O + ((size_t)b * SEQ + gr0) * DMODEL + (h << 6);
    __half* Og1 = g_O + ((size_t)b * SEQ + gr1) * DMODEL + (h << 6);
#pragma unroll
    for (int nf = 0; nf < 8; nf++) {
        int c = (nf << 3) + (tg << 1);
        *(__half2*)&Og0[c] = __floats2half2_rn(of[nf][0] * inv0, of[nf][1] * inv0);
        *(__half2*)&Og1[c] = __floats2half2_rn(of[nf][2] * inv1, of[nf][3] * inv1);
    }
}

// ---------------------------------------------------------------------------
extern "C" void kernel_launch(void* const* d_in, const int* in_sizes, int n_in,
                              void* d_out, int out_size)
{
    const float* query = (const float*)d_in[0];
    const float* key   = (const float*)d_in[1];
    const float* value = (const float*)d_in[2];
    const unsigned char* mask = (const unsigned char*)d_in[3];
    const float* Wq    = (const float*)d_in[4];
    const float* Wk    = (const float*)d_in[5];
    const float* Wv    = (const float*)d_in[6];
    const float* Wout  = (const float*)d_in[7];
    const float* b_out = (const float*)d_in[8];
    const int* is_causal = (const int*)d_in[9];
    float* out = (float*)d_out;

    cudaFuncSetAttribute(attn_mma_kernel,
                         cudaFuncAttributeMaxDynamicSharedMemorySize, ATTN_SMEM_BYTES);
    cudaFuncSetAttribute(gemm_qkv_kernel,
                         cudaFuncAttributeMaxDynamicSharedMemorySize, GEMM_SMEM_BYTES);
    cudaFuncSetAttribute(gemm_out_kernel,
                         cudaFuncAttributeMaxDynamicSharedMemorySize, GEMM_SMEM_BYTES);

    // prepass: round inputs + weights to fp16 in scratch
    dim3 rgrid((MROWS * DMODEL / 4 + 255) / 256, 7);   // (4096, 7)
    round_f16_kernel<<<rgrid, 256>>>(query, key, value, Wq, Wk, Wv, Wout);

    dim3 qkvgrid(DMODEL / 128, MROWS / 128, 3);   // (8, 32, 3)
    gemm_qkv_kernel<<<qkvgrid, 256, GEMM_SMEM_BYTES>>>();

    // attention: 1D grid, globally heavy-first (qt descending with bid)
    attn_mma_kernel<<<(SEQ / 128) * BATCH * NHEAD, 256, ATTN_SMEM_BYTES>>>(mask, is_causal);

    dim3 ogrid(DMODEL / 128, MROWS / 128);        // (8, 32)
    gemm_out_kernel<<<ogrid, 256, GEMM_SMEM_BYTES>>>(b_out, out);
}